// round 10
// baseline (speedup 1.0000x reference)
#include <cuda_runtime.h>
#include <cuda_bf16.h>
#include <cstdint>
#include <math.h>

// x [4096,256] fp32, y [16384,256] fp32 -> out[i,j] = ||x_i - y_j|| [4096,16384] fp32
// d2 = x2[i] + y2[j] - 2*dot(x_i,y_j); dot via mma.sync bf16 (HMMA on sm_103).
// CTA tile 128x128, warp tile 64x32, K in 4 chunks of 64, 3-stage cp.async pipeline,
// __launch_bounds__(256,2) to keep regs <=128 -> 2 CTAs/SM.

#define NX 4096
#define NY 16384
#define KD 256

#define BM 128
#define BN 128
#define BK 64
#define KCHUNKS (KD / BK)
#define STAGES 3

// ---- device scratch ----
__device__ __align__(256) __nv_bfloat16 g_xb[NX * KD];
__device__ __align__(256) __nv_bfloat16 g_yb[NY * KD];
__device__ float g_x2[NX];
__device__ float g_y2[NY];

// ---- SMEM layout ----
#define OFF_SX2   0                  // 128 floats
#define OFF_SY2   512                // 128 floats
#define OFF_TILES 1024
#define STAGE_BYTES 32768            // A 16KB + B 16KB
#define SMEM_TOTAL (OFF_TILES + STAGES * STAGE_BYTES)   // 99328

__device__ __forceinline__ uint32_t smem_u32(const void* p) {
    uint32_t a;
    asm("{ .reg .u64 t; cvta.to.shared.u64 t, %1; cvt.u32.u64 %0, t; }" : "=r"(a) : "l"(p));
    return a;
}
__device__ __forceinline__ uint32_t swz(uint32_t off) {   // SW128
    return off ^ ((off >> 3) & 0x70);
}
#define CP16(dst, src) asm volatile("cp.async.cg.shared.global [%0], [%1], 16;" :: "r"(dst), "l"(src) : "memory")
#define CP_COMMIT()    asm volatile("cp.async.commit_group;" ::: "memory")

__device__ __forceinline__ void ldmx4(uint32_t* r, uint32_t addr) {
    asm volatile("ldmatrix.sync.aligned.m8n8.x4.shared.b16 {%0,%1,%2,%3}, [%4];"
        : "=r"(r[0]), "=r"(r[1]), "=r"(r[2]), "=r"(r[3]) : "r"(addr));
}
__device__ __forceinline__ void mma16816(float* c, const uint32_t* a, uint32_t b0, uint32_t b1) {
    asm volatile("mma.sync.aligned.m16n8k16.row.col.f32.bf16.bf16.f32 "
        "{%0,%1,%2,%3}, {%4,%5,%6,%7}, {%8,%9}, {%0,%1,%2,%3};"
        : "+f"(c[0]), "+f"(c[1]), "+f"(c[2]), "+f"(c[3])
        : "r"(a[0]), "r"(a[1]), "r"(a[2]), "r"(a[3]), "r"(b0), "r"(b1));
}

// ---- fused conversion + row-norm kernel: rows [0,NX) -> x, [NX,NX+NY) -> y ----
__global__ void convert_norm_all(const float* __restrict__ x, const float* __restrict__ y) {
    int row = blockIdx.x * (blockDim.x >> 5) + (threadIdx.x >> 5);
    int lane = threadIdx.x & 31;
    const float* src;
    __nv_bfloat16* dst;
    float* nrm;
    int r;
    if (row < NX) { src = x; dst = g_xb; nrm = g_x2; r = row; }
    else          { src = y; dst = g_yb; nrm = g_y2; r = row - NX; }
    const float4* p = reinterpret_cast<const float4*>(src + (size_t)r * KD);
    float4 a = p[lane * 2];
    float4 b = p[lane * 2 + 1];
    float s = a.x * a.x + a.y * a.y + a.z * a.z + a.w * a.w
            + b.x * b.x + b.y * b.y + b.z * b.z + b.w * b.w;
    __nv_bfloat162 h0 = __float22bfloat162_rn(make_float2(a.x, a.y));
    __nv_bfloat162 h1 = __float22bfloat162_rn(make_float2(a.z, a.w));
    __nv_bfloat162 h2 = __float22bfloat162_rn(make_float2(b.x, b.y));
    __nv_bfloat162 h3 = __float22bfloat162_rn(make_float2(b.z, b.w));
    uint4 u;
    u.x = reinterpret_cast<unsigned&>(h0);
    u.y = reinterpret_cast<unsigned&>(h1);
    u.z = reinterpret_cast<unsigned&>(h2);
    u.w = reinterpret_cast<unsigned&>(h3);
    reinterpret_cast<uint4*>(dst + (size_t)r * KD)[lane] = u;
    #pragma unroll
    for (int o = 16; o > 0; o >>= 1) s += __shfl_xor_sync(0xFFFFFFFFu, s, o);
    if (lane == 0) nrm[r] = s;
}

// ---- main bf16 HMMA distance kernel ----
__global__ __launch_bounds__(256, 2)
void dist_mma_kernel(float* __restrict__ out) {
    extern __shared__ char smem[];
    const uint32_t sb = smem_u32(smem);
    const int tid = threadIdx.x;
    const int lane = tid & 31;
    const int wid = tid >> 5;
    const int warp_m = wid >> 2;          // 0..1  -> 64-row slab
    const int warp_n = wid & 3;           // 0..3  -> 32-col slab
    const int bm = blockIdx.y * BM;
    const int bn = blockIdx.x * BN;

    float* sx2 = reinterpret_cast<float*>(smem + OFF_SX2);
    float* sy2 = reinterpret_cast<float*>(smem + OFF_SY2);
    if (tid < 128) sx2[tid] = g_x2[bm + tid];
    else           sy2[tid - 128] = g_y2[bn + tid - 128];

    // ---- global -> smem prefetch of one K chunk into one stage ----
    const int lrow  = tid >> 1;            // 0..127
    const int lhalf = (tid & 1) * 64;      // byte offset within 128B row
    const char* xsrc = reinterpret_cast<const char*>(g_xb) + (size_t)(bm + lrow) * (KD * 2) + lhalf;
    const char* ysrc = reinterpret_cast<const char*>(g_yb) + (size_t)(bn + lrow) * (KD * 2) + lhalf;
    const uint32_t rowbase = (uint32_t)lrow * 128 + (uint32_t)lhalf;

    auto prefetch = [&](int chunk, int stage) {
        uint32_t sA = sb + OFF_TILES + stage * STAGE_BYTES;
        uint32_t sB = sA + 16384;
        const char* xs = xsrc + chunk * 128;
        const char* ys = ysrc + chunk * 128;
        #pragma unroll
        for (int i = 0; i < 4; i++) {
            uint32_t sw = swz(rowbase + i * 16);
            CP16(sA + sw, xs + i * 16);
            CP16(sB + sw, ys + i * 16);
        }
    };

    prefetch(0, 0); CP_COMMIT();
    prefetch(1, 1); CP_COMMIT();
    prefetch(2, 2); CP_COMMIT();

    float acc[4][4][4];
    #pragma unroll
    for (int i = 0; i < 4; i++)
        #pragma unroll
        for (int j = 0; j < 4; j++)
            #pragma unroll
            for (int k = 0; k < 4; k++) acc[i][j][k] = 0.0f;

    const uint32_t lrow16 = (uint32_t)(lane & 15);
    const uint32_t lkoff  = (uint32_t)((lane >> 4) << 4);

    #pragma unroll
    for (int c = 0; c < KCHUNKS; c++) {
        // wait until chunk c's group is complete (groups committed: up to c+2 / 3)
        if (c == 0 || c == 1) asm volatile("cp.async.wait_group 2;" ::: "memory");
        else if (c == 2)      asm volatile("cp.async.wait_group 1;" ::: "memory");
        else                  asm volatile("cp.async.wait_group 0;" ::: "memory");
        __syncthreads();

        const int stage = c % STAGES;
        uint32_t sA = sb + OFF_TILES + stage * STAGE_BYTES;
        uint32_t sB = sA + 16384;

        #pragma unroll
        for (int ks = 0; ks < 4; ks++) {           // 4 k16 steps per 64-chunk
            const uint32_t kb = ks * 32 + lkoff;
            uint32_t a[4][4];
            #pragma unroll
            for (int mm = 0; mm < 4; mm++) {
                uint32_t row = warp_m * 64 + mm * 16 + lrow16;
                ldmx4(a[mm], sA + swz(row * 128 + kb));
            }
            uint32_t b[2][4];
            #pragma unroll
            for (int np = 0; np < 2; np++) {
                uint32_t row = warp_n * 32 + np * 16 + lrow16;
                ldmx4(b[np], sB + swz(row * 128 + kb));
            }
            #pragma unroll
            for (int mm = 0; mm < 4; mm++)
                #pragma unroll
                for (int nn = 0; nn < 4; nn++) {
                    const int np = nn >> 1, hi = nn & 1;
                    mma16816(acc[mm][nn], a[mm], b[np][hi ? 1 : 0], b[np][hi ? 3 : 2]);
                }
        }

        if (c + STAGES < KCHUNKS + STAGES - 1) {   // more chunks to load?
            if (c + STAGES < KCHUNKS) {
                __syncthreads();                   // all warps done reading this stage
                prefetch(c + STAGES, stage);
            }
            CP_COMMIT();
        }
    }

    // ---- epilogue: d = sqrt(max(x2 + y2 - 2*acc, 0)) ----
    const int t4 = lane >> 2;        // 0..7
    const int tc = (lane & 3) * 2;   // 0,2,4,6
    #pragma unroll
    for (int mm = 0; mm < 4; mm++) {
        const int r0 = warp_m * 64 + mm * 16 + t4;
        const float x2a = sx2[r0];
        const float x2b = sx2[r0 + 8];
        float* orow0 = out + (size_t)(bm + r0) * NY + bn;
        float* orow1 = orow0 + (size_t)8 * NY;
        #pragma unroll
        for (int nn = 0; nn < 4; nn++) {
            const int col = warp_n * 32 + nn * 8 + tc;
            const float y2a = sy2[col];
            const float y2b = sy2[col + 1];
            float d0 = fmaxf(fmaf(-2.0f, acc[mm][nn][0], x2a + y2a), 0.0f);
            float d1 = fmaxf(fmaf(-2.0f, acc[mm][nn][1], x2a + y2b), 0.0f);
            float d2 = fmaxf(fmaf(-2.0f, acc[mm][nn][2], x2b + y2a), 0.0f);
            float d3 = fmaxf(fmaf(-2.0f, acc[mm][nn][3], x2b + y2b), 0.0f);
            float2 o0, o1;
            asm("sqrt.approx.f32 %0, %1;" : "=f"(o0.x) : "f"(d0));
            asm("sqrt.approx.f32 %0, %1;" : "=f"(o0.y) : "f"(d1));
            asm("sqrt.approx.f32 %0, %1;" : "=f"(o1.x) : "f"(d2));
            asm("sqrt.approx.f32 %0, %1;" : "=f"(o1.y) : "f"(d3));
            *reinterpret_cast<float2*>(orow0 + col) = o0;
            *reinterpret_cast<float2*>(orow1 + col) = o1;
        }
    }
}

extern "C" void kernel_launch(void* const* d_in, const int* in_sizes, int n_in,
                              void* d_out, int out_size) {
    const float* x = (const float*)d_in[0];   // [4096, 256]
    const float* y = (const float*)d_in[1];   // [16384, 256]
    float* out = (float*)d_out;               // [4096, 16384]

    convert_norm_all<<<(NX + NY) / 8, 256>>>(x, y);

    cudaFuncSetAttribute(dist_mma_kernel, cudaFuncAttributeMaxDynamicSharedMemorySize, SMEM_TOTAL);
    dim3 grid(NY / BN, NX / BM);  // (128, 32)
    dist_mma_kernel<<<grid, 256, SMEM_TOTAL>>>(out);
}

// round 11
// speedup vs baseline: 1.4940x; 1.4940x over previous
#include <cuda_runtime.h>
#include <cuda_bf16.h>
#include <cstdint>
#include <math.h>

// x [4096,256] fp32, y [16384,256] fp32 -> out[i,j] = ||x_i - y_j|| [4096,16384] fp32
// d2 = x2[i] + y2[j] - 2*dot(x_i,y_j); dot via mma.sync bf16 (HMMA on sm_103).
// R5-proven geometry: CTA tile 128x128, warp tile 64x32, K in 4 chunks of 64,
// 2-stage cp.async pipeline, __launch_bounds__(256,2) -> 2 CTAs/SM.

#define NX 4096
#define NY 16384
#define KD 256

#define BM 128
#define BN 128
#define BK 64
#define KCHUNKS (KD / BK)

// ---- device scratch ----
__device__ __align__(256) __nv_bfloat16 g_xb[NX * KD];
__device__ __align__(256) __nv_bfloat16 g_yb[NY * KD];
__device__ float g_x2[NX];
__device__ float g_y2[NY];

// ---- SMEM layout ----
#define OFF_SX2   0                  // 128 floats
#define OFF_SY2   512                // 128 floats
#define OFF_TILES 1024
#define STAGE_BYTES 32768            // A 16KB + B 16KB
#define SMEM_TOTAL (OFF_TILES + 2 * STAGE_BYTES)   // 66560

__device__ __forceinline__ uint32_t smem_u32(const void* p) {
    uint32_t a;
    asm("{ .reg .u64 t; cvta.to.shared.u64 t, %1; cvt.u32.u64 %0, t; }" : "=r"(a) : "l"(p));
    return a;
}
__device__ __forceinline__ uint32_t swz(uint32_t off) {   // SW128
    return off ^ ((off >> 3) & 0x70);
}
#define CP16(dst, src) asm volatile("cp.async.cg.shared.global [%0], [%1], 16;" :: "r"(dst), "l"(src) : "memory")
#define CP_COMMIT()    asm volatile("cp.async.commit_group;" ::: "memory")
#define CP_WAIT1()     asm volatile("cp.async.wait_group 1;" ::: "memory")

__device__ __forceinline__ void ldmx4(uint32_t* r, uint32_t addr) {
    asm volatile("ldmatrix.sync.aligned.m8n8.x4.shared.b16 {%0,%1,%2,%3}, [%4];"
        : "=r"(r[0]), "=r"(r[1]), "=r"(r[2]), "=r"(r[3]) : "r"(addr));
}
__device__ __forceinline__ void mma16816(float* c, const uint32_t* a, uint32_t b0, uint32_t b1) {
    asm volatile("mma.sync.aligned.m16n8k16.row.col.f32.bf16.bf16.f32 "
        "{%0,%1,%2,%3}, {%4,%5,%6,%7}, {%8,%9}, {%0,%1,%2,%3};"
        : "+f"(c[0]), "+f"(c[1]), "+f"(c[2]), "+f"(c[3])
        : "r"(a[0]), "r"(a[1]), "r"(a[2]), "r"(a[3]), "r"(b0), "r"(b1));
}

// ---- fused conversion + row-norm kernel: rows [0,NX) -> x, [NX,NX+NY) -> y ----
__global__ void convert_norm_all(const float* __restrict__ x, const float* __restrict__ y) {
    int row = blockIdx.x * (blockDim.x >> 5) + (threadIdx.x >> 5);
    int lane = threadIdx.x & 31;
    const float* src;
    __nv_bfloat16* dst;
    float* nrm;
    int r;
    if (row < NX) { src = x; dst = g_xb; nrm = g_x2; r = row; }
    else          { src = y; dst = g_yb; nrm = g_y2; r = row - NX; }
    const float4* p = reinterpret_cast<const float4*>(src + (size_t)r * KD);
    float4 a = p[lane * 2];
    float4 b = p[lane * 2 + 1];
    float s = a.x * a.x + a.y * a.y + a.z * a.z + a.w * a.w
            + b.x * b.x + b.y * b.y + b.z * b.z + b.w * b.w;
    __nv_bfloat162 h0 = __float22bfloat162_rn(make_float2(a.x, a.y));
    __nv_bfloat162 h1 = __float22bfloat162_rn(make_float2(a.z, a.w));
    __nv_bfloat162 h2 = __float22bfloat162_rn(make_float2(b.x, b.y));
    __nv_bfloat162 h3 = __float22bfloat162_rn(make_float2(b.z, b.w));
    uint4 u;
    u.x = reinterpret_cast<unsigned&>(h0);
    u.y = reinterpret_cast<unsigned&>(h1);
    u.z = reinterpret_cast<unsigned&>(h2);
    u.w = reinterpret_cast<unsigned&>(h3);
    reinterpret_cast<uint4*>(dst + (size_t)r * KD)[lane] = u;
    #pragma unroll
    for (int o = 16; o > 0; o >>= 1) s += __shfl_xor_sync(0xFFFFFFFFu, s, o);
    if (lane == 0) nrm[r] = s;
}

// ---- main bf16 HMMA distance kernel (R5 structure) ----
__global__ __launch_bounds__(256, 2)
void dist_mma_kernel(float* __restrict__ out) {
    extern __shared__ char smem[];
    const uint32_t sb = smem_u32(smem);
    const int tid = threadIdx.x;
    const int lane = tid & 31;
    const int wid = tid >> 5;
    const int warp_m = wid >> 2;          // 0..1  -> 64-row slab
    const int warp_n = wid & 3;           // 0..3  -> 32-col slab
    const int bm = blockIdx.y * BM;
    const int bn = blockIdx.x * BN;

    float* sx2 = reinterpret_cast<float*>(smem + OFF_SX2);
    float* sy2 = reinterpret_cast<float*>(smem + OFF_SY2);
    if (tid < 128) sx2[tid] = g_x2[bm + tid];
    else           sy2[tid - 128] = g_y2[bn + tid - 128];

    // ---- global -> smem prefetch of one K chunk into one stage ----
    const int lrow  = tid >> 1;            // 0..127
    const int lhalf = (tid & 1) * 64;      // byte offset within 128B row
    const char* xsrc = reinterpret_cast<const char*>(g_xb) + (size_t)(bm + lrow) * (KD * 2) + lhalf;
    const char* ysrc = reinterpret_cast<const char*>(g_yb) + (size_t)(bn + lrow) * (KD * 2) + lhalf;
    const uint32_t rowbase = (uint32_t)lrow * 128 + (uint32_t)lhalf;

    auto prefetch = [&](int chunk, int stage) {
        uint32_t sA = sb + OFF_TILES + stage * STAGE_BYTES;
        uint32_t sB = sA + 16384;
        const char* xs = xsrc + chunk * 128;
        const char* ys = ysrc + chunk * 128;
        #pragma unroll
        for (int i = 0; i < 4; i++) {
            uint32_t sw = swz(rowbase + i * 16);
            CP16(sA + sw, xs + i * 16);
            CP16(sB + sw, ys + i * 16);
        }
    };

    prefetch(0, 0); CP_COMMIT();
    prefetch(1, 1); CP_COMMIT();

    float acc[4][4][4];
    #pragma unroll
    for (int i = 0; i < 4; i++)
        #pragma unroll
        for (int j = 0; j < 4; j++)
            #pragma unroll
            for (int k = 0; k < 4; k++) acc[i][j][k] = 0.0f;

    const uint32_t lrow16 = (uint32_t)(lane & 15);
    const uint32_t lkoff  = (uint32_t)((lane >> 4) << 4);

    #pragma unroll
    for (int c = 0; c < KCHUNKS; c++) {
        CP_WAIT1();
        __syncthreads();
        const int stage = c & 1;
        uint32_t sA = sb + OFF_TILES + stage * STAGE_BYTES;
        uint32_t sB = sA + 16384;

        #pragma unroll
        for (int ks = 0; ks < 4; ks++) {           // 4 k16 steps per 64-chunk
            const uint32_t kb = ks * 32 + lkoff;
            uint32_t a[4][4];
            #pragma unroll
            for (int mm = 0; mm < 4; mm++) {
                uint32_t row = warp_m * 64 + mm * 16 + lrow16;
                ldmx4(a[mm], sA + swz(row * 128 + kb));
            }
            uint32_t b[2][4];
            #pragma unroll
            for (int np = 0; np < 2; np++) {
                uint32_t row = warp_n * 32 + np * 16 + lrow16;
                ldmx4(b[np], sB + swz(row * 128 + kb));
            }
            #pragma unroll
            for (int mm = 0; mm < 4; mm++)
                #pragma unroll
                for (int nn = 0; nn < 4; nn++) {
                    const int np = nn >> 1, hi = nn & 1;
                    mma16816(acc[mm][nn], a[mm], b[np][hi ? 1 : 0], b[np][hi ? 3 : 2]);
                }
        }
        __syncthreads();
        if (c + 2 < KCHUNKS) prefetch(c + 2, stage);
        CP_COMMIT();
    }

    // ---- epilogue: d = sqrt(max(x2 + y2 - 2*acc, 0)) ----
    const int t4 = lane >> 2;        // 0..7
    const int tc = (lane & 3) * 2;   // 0,2,4,6
    #pragma unroll
    for (int mm = 0; mm < 4; mm++) {
        const int r0 = warp_m * 64 + mm * 16 + t4;
        const float x2a = sx2[r0];
        const float x2b = sx2[r0 + 8];
        float* orow0 = out + (size_t)(bm + r0) * NY + bn;
        float* orow1 = orow0 + (size_t)8 * NY;
        #pragma unroll
        for (int nn = 0; nn < 4; nn++) {
            const int col = warp_n * 32 + nn * 8 + tc;
            const float y2a = sy2[col];
            const float y2b = sy2[col + 1];
            float d0 = fmaxf(fmaf(-2.0f, acc[mm][nn][0], x2a + y2a), 0.0f);
            float d1 = fmaxf(fmaf(-2.0f, acc[mm][nn][1], x2a + y2b), 0.0f);
            float d2 = fmaxf(fmaf(-2.0f, acc[mm][nn][2], x2b + y2a), 0.0f);
            float d3 = fmaxf(fmaf(-2.0f, acc[mm][nn][3], x2b + y2b), 0.0f);
            float2 o0, o1;
            asm("sqrt.approx.f32 %0, %1;" : "=f"(o0.x) : "f"(d0));
            asm("sqrt.approx.f32 %0, %1;" : "=f"(o0.y) : "f"(d1));
            asm("sqrt.approx.f32 %0, %1;" : "=f"(o1.x) : "f"(d2));
            asm("sqrt.approx.f32 %0, %1;" : "=f"(o1.y) : "f"(d3));
            *reinterpret_cast<float2*>(orow0 + col) = o0;
            *reinterpret_cast<float2*>(orow1 + col) = o1;
        }
    }
}

extern "C" void kernel_launch(void* const* d_in, const int* in_sizes, int n_in,
                              void* d_out, int out_size) {
    const float* x = (const float*)d_in[0];   // [4096, 256]
    const float* y = (const float*)d_in[1];   // [16384, 256]
    float* out = (float*)d_out;               // [4096, 16384]

    convert_norm_all<<<(NX + NY) / 8, 256>>>(x, y);

    cudaFuncSetAttribute(dist_mma_kernel, cudaFuncAttributeMaxDynamicSharedMemorySize, SMEM_TOTAL);
    dim3 grid(NY / BN, NX / BM);  // (128, 32)
    dist_mma_kernel<<<grid, 256, SMEM_TOTAL>>>(out);
}

// round 14
// speedup vs baseline: 1.6184x; 1.0832x over previous
#include <cuda_runtime.h>
#include <cuda_bf16.h>
#include <cstdint>
#include <math.h>

// x [4096,256] fp32, y [16384,256] fp32 -> out[i,j] = ||x_i - y_j|| [4096,16384] fp32
// d2 = x2[i] + y2[j] - 2*dot(x_i,y_j); dot via mma.sync bf16 (HMMA on sm_103).
// B-resident persistent CTA: B tile (128 cols x K=256, 64KB) stays in smem;
// CTA processes TILES=2 row-tiles of A streamed in 16KB chunks (2-stage cp.async).
// Warp tile 64x32, __launch_bounds__(256,2) -> 2 CTAs/SM.

#define NX 4096
#define NY 16384
#define KD 256

#define BM 128
#define BN 128
#define BK 64
#define KCHUNKS (KD / BK)
#define TILES 2

// ---- device scratch ----
__device__ __align__(256) __nv_bfloat16 g_xb[NX * KD];
__device__ __align__(256) __nv_bfloat16 g_yb[NY * KD];
__device__ float g_x2[NX];
__device__ float g_y2[NY];

// ---- SMEM layout ----
#define OFF_SY2   0                   // 128 floats
#define OFF_B     1024                // 4 chunks x 16384 B (resident, full K)
#define OFF_A     (OFF_B + 65536)     // 2 stages x 16384 B
#define SMEM_TOTAL (OFF_A + 2 * 16384)   // 99328

__device__ __forceinline__ uint32_t smem_u32(const void* p) {
    uint32_t a;
    asm("{ .reg .u64 t; cvta.to.shared.u64 t, %1; cvt.u32.u64 %0, t; }" : "=r"(a) : "l"(p));
    return a;
}
__device__ __forceinline__ uint32_t swz(uint32_t off) {   // SW128
    return off ^ ((off >> 3) & 0x70);
}
#define CP16(dst, src) asm volatile("cp.async.cg.shared.global [%0], [%1], 16;" :: "r"(dst), "l"(src) : "memory")
#define CP_COMMIT()    asm volatile("cp.async.commit_group;" ::: "memory")

__device__ __forceinline__ void ldmx4(uint32_t* r, uint32_t addr) {
    asm volatile("ldmatrix.sync.aligned.m8n8.x4.shared.b16 {%0,%1,%2,%3}, [%4];"
        : "=r"(r[0]), "=r"(r[1]), "=r"(r[2]), "=r"(r[3]) : "r"(addr));
}
__device__ __forceinline__ void mma16816(float* c, const uint32_t* a, uint32_t b0, uint32_t b1) {
    asm volatile("mma.sync.aligned.m16n8k16.row.col.f32.bf16.bf16.f32 "
        "{%0,%1,%2,%3}, {%4,%5,%6,%7}, {%8,%9}, {%0,%1,%2,%3};"
        : "+f"(c[0]), "+f"(c[1]), "+f"(c[2]), "+f"(c[3])
        : "r"(a[0]), "r"(a[1]), "r"(a[2]), "r"(a[3]), "r"(b0), "r"(b1));
}

// ---- fused conversion + row-norm kernel: rows [0,NX) -> x, [NX,NX+NY) -> y ----
__global__ void convert_norm_all(const float* __restrict__ x, const float* __restrict__ y) {
    int row = blockIdx.x * (blockDim.x >> 5) + (threadIdx.x >> 5);
    int lane = threadIdx.x & 31;
    const float* src;
    __nv_bfloat16* dst;
    float* nrm;
    int r;
    if (row < NX) { src = x; dst = g_xb; nrm = g_x2; r = row; }
    else          { src = y; dst = g_yb; nrm = g_y2; r = row - NX; }
    const float4* p = reinterpret_cast<const float4*>(src + (size_t)r * KD);
    float4 a = p[lane * 2];
    float4 b = p[lane * 2 + 1];
    float s = a.x * a.x + a.y * a.y + a.z * a.z + a.w * a.w
            + b.x * b.x + b.y * b.y + b.z * b.z + b.w * b.w;
    __nv_bfloat162 h0 = __float22bfloat162_rn(make_float2(a.x, a.y));
    __nv_bfloat162 h1 = __float22bfloat162_rn(make_float2(a.z, a.w));
    __nv_bfloat162 h2 = __float22bfloat162_rn(make_float2(b.x, b.y));
    __nv_bfloat162 h3 = __float22bfloat162_rn(make_float2(b.z, b.w));
    uint4 u;
    u.x = reinterpret_cast<unsigned&>(h0);
    u.y = reinterpret_cast<unsigned&>(h1);
    u.z = reinterpret_cast<unsigned&>(h2);
    u.w = reinterpret_cast<unsigned&>(h3);
    reinterpret_cast<uint4*>(dst + (size_t)r * KD)[lane] = u;
    #pragma unroll
    for (int o = 16; o > 0; o >>= 1) s += __shfl_xor_sync(0xFFFFFFFFu, s, o);
    if (lane == 0) nrm[r] = s;
}

// ---- main bf16 HMMA distance kernel (B-resident, persistent over TILES row-tiles) ----
__global__ __launch_bounds__(256, 2)
void dist_mma_kernel(float* __restrict__ out) {
    extern __shared__ char smem[];
    const uint32_t sb = smem_u32(smem);
    const int tid = threadIdx.x;
    const int lane = tid & 31;
    const int wid = tid >> 5;
    const int warp_m = wid >> 2;          // 0..1  -> 64-row slab
    const int warp_n = wid & 3;           // 0..3  -> 32-col slab
    const int bn  = blockIdx.x * BN;
    const int bm0 = blockIdx.y * (BM * TILES);

    float* sy2 = reinterpret_cast<float*>(smem + OFF_SY2);
    if (tid < 128) sy2[tid] = g_y2[bn + tid];

    // ---- cp.async source mapping: thread covers row lrow, 64B half lhalf ----
    const int lrow  = tid >> 1;            // 0..127
    const int lhalf = (tid & 1) * 64;      // byte offset within 128B (=64 bf16) chunk-row
    const char* xbase = reinterpret_cast<const char*>(g_xb) + (size_t)(bm0 + lrow) * (KD * 2) + lhalf;
    const char* ybase = reinterpret_cast<const char*>(g_yb) + (size_t)(bn  + lrow) * (KD * 2) + lhalf;
    const uint32_t rowbase = (uint32_t)lrow * 128 + (uint32_t)lhalf;

    auto loadB = [&](int c) {
        uint32_t sB = sb + OFF_B + c * 16384;
        const char* ys = ybase + c * 128;
        #pragma unroll
        for (int i = 0; i < 4; i++)
            CP16(sB + swz(rowbase + i * 16), ys + i * 16);
    };
    auto loadA = [&](int t, int c, int stage) {
        uint32_t sA = sb + OFF_A + stage * 16384;
        const char* xs = xbase + (size_t)t * (BM * KD * 2) + c * 128;
        #pragma unroll
        for (int i = 0; i < 4; i++)
            CP16(sA + swz(rowbase + i * 16), xs + i * 16);
    };

    // Prologue: progressive groups so first MMA waits only on B0+A0.
    loadB(0); loadA(0, 0, 0); CP_COMMIT();   // G0
    loadB(1); loadA(0, 1, 1); CP_COMMIT();   // G1
    loadB(2); CP_COMMIT();                   // G2
    loadB(3); CP_COMMIT();                   // G3

    const uint32_t lrow16 = (uint32_t)(lane & 15);
    const uint32_t lkoff  = (uint32_t)((lane >> 4) << 4);
    const int t4 = lane >> 2;        // 0..7
    const int tc = (lane & 3) * 2;   // 0,2,4,6

    #pragma unroll 1
    for (int t = 0; t < TILES; t++) {
        float acc[4][4][4];
        #pragma unroll
        for (int i = 0; i < 4; i++)
            #pragma unroll
            for (int j = 0; j < 4; j++)
                #pragma unroll
                for (int k = 0; k < 4; k++) acc[i][j][k] = 0.0f;

        #pragma unroll
        for (int c = 0; c < KCHUNKS; c++) {
            // A chunk g=t*4+c lives in group g (g<2) or g+2 (g>=2); B chunk c in group c.
            if (t == 0 && c < 2) asm volatile("cp.async.wait_group 3;" ::: "memory");
            else                 asm volatile("cp.async.wait_group 1;" ::: "memory");
            __syncthreads();

            const int stage = c & 1;                 // (t*4+c)&1 == c&1 since 4t even
            uint32_t sA = sb + OFF_A + stage * 16384;
            uint32_t sB = sb + OFF_B + c * 16384;

            #pragma unroll
            for (int ks = 0; ks < 4; ks++) {         // 4 k16 steps per 64-chunk
                const uint32_t kb = ks * 32 + lkoff;
                uint32_t a[4][4];
                #pragma unroll
                for (int mm = 0; mm < 4; mm++) {
                    uint32_t row = warp_m * 64 + mm * 16 + lrow16;
                    ldmx4(a[mm], sA + swz(row * 128 + kb));
                }
                uint32_t b[2][4];
                #pragma unroll
                for (int np = 0; np < 2; np++) {
                    uint32_t row = warp_n * 32 + np * 16 + lrow16;
                    ldmx4(b[np], sB + swz(row * 128 + kb));
                }
                #pragma unroll
                for (int mm = 0; mm < 4; mm++)
                    #pragma unroll
                    for (int nn = 0; nn < 4; nn++) {
                        const int np = nn >> 1, hi = nn & 1;
                        mma16816(acc[mm][nn], a[mm], b[np][hi ? 1 : 0], b[np][hi ? 3 : 2]);
                    }
            }
            __syncthreads();

            // Prefetch A chunk g+2 into the stage just consumed.
            if (c < 2)                 loadA(t,     c + 2, stage);
            else if (t < TILES - 1)    loadA(t + 1, c - 2, stage);
            CP_COMMIT();
        }

        // ---- epilogue for tile t: d = sqrt(max(x2 + y2 - 2*acc, 0)) ----
        const int bm = bm0 + t * BM;
        #pragma unroll
        for (int mm = 0; mm < 4; mm++) {
            const int r0 = warp_m * 64 + mm * 16 + t4;
            const float x2a = g_x2[bm + r0];
            const float x2b = g_x2[bm + r0 + 8];
            float* orow0 = out + (size_t)(bm + r0) * NY + bn;
            float* orow1 = orow0 + (size_t)8 * NY;
            #pragma unroll
            for (int nn = 0; nn < 4; nn++) {
                const int col = warp_n * 32 + nn * 8 + tc;
                const float y2a = sy2[col];
                const float y2b = sy2[col + 1];
                float d0 = fmaxf(fmaf(-2.0f, acc[mm][nn][0], x2a + y2a), 0.0f);
                float d1 = fmaxf(fmaf(-2.0f, acc[mm][nn][1], x2a + y2b), 0.0f);
                float d2 = fmaxf(fmaf(-2.0f, acc[mm][nn][2], x2b + y2a), 0.0f);
                float d3 = fmaxf(fmaf(-2.0f, acc[mm][nn][3], x2b + y2b), 0.0f);
                float2 o0, o1;
                asm("sqrt.approx.f32 %0, %1;" : "=f"(o0.x) : "f"(d0));
                asm("sqrt.approx.f32 %0, %1;" : "=f"(o0.y) : "f"(d1));
                asm("sqrt.approx.f32 %0, %1;" : "=f"(o1.x) : "f"(d2));
                asm("sqrt.approx.f32 %0, %1;" : "=f"(o1.y) : "f"(d3));
                *reinterpret_cast<float2*>(orow0 + col) = o0;
                *reinterpret_cast<float2*>(orow1 + col) = o1;
            }
        }
    }
}

extern "C" void kernel_launch(void* const* d_in, const int* in_sizes, int n_in,
                              void* d_out, int out_size) {
    const float* x = (const float*)d_in[0];   // [4096, 256]
    const float* y = (const float*)d_in[1];   // [16384, 256]
    float* out = (float*)d_out;               // [4096, 16384]

    convert_norm_all<<<(NX + NY) / 8, 256>>>(x, y);

    cudaFuncSetAttribute(dist_mma_kernel, cudaFuncAttributeMaxDynamicSharedMemorySize, SMEM_TOTAL);
    dim3 grid(NY / BN, NX / (BM * TILES));  // (128, 16) = 2048 CTAs
    dist_mma_kernel<<<grid, 256, SMEM_TOTAL>>>(out);
}